// round 12
// baseline (speedup 1.0000x reference)
#include <cuda_runtime.h>
#include <cstdint>
#include <cstdio>

// Problem constants (fixed by the reference)
#define Nn 100000
#define Ee 1600000
#define Hh 64
#define Gg 64

// ---------------- static device scratch (no allocations allowed) ----------------
__device__ int      g_cnt[Nn];        // per-row edge count
__device__ int      g_ptr[Nn + 1];    // CSR row pointers
__device__ int      g_fill[Nn];       // scatter cursors
__device__ float    g_dis[Nn];        // deg^{-1/2}
__device__ int      g_ccol[Ee];       // CSR col indices
__device__ float    g_cnorm[Ee];      // CSR edge weights (-dis[r]*dis[c])
__device__ float    g_T1 [Nn * Hh];
__device__ float    g_Tmp[Nn * Hh];
__device__ float    g_hpre[Nn * Hh];
__device__ float    g_h  [Nn * Hh];
__device__ float    g_sc [Nn * Hh];
__device__ float    g_Wc [192 * 64];
__device__ float    g_stats[128];     // [0:64) sum, [64:128) sumsq
__device__ float    g_ab[128];        // [0:64) scale a, [64:128) shift c
__device__ unsigned g_pool[Gg * 64];

// ---------------- helpers ----------------
__device__ __forceinline__ unsigned enc_f(float f) {
    unsigned u = __float_as_uint(f);
    return (u & 0x80000000u) ? ~u : (u | 0x80000000u);
}
__device__ __forceinline__ float dec_f(unsigned u) {
    return (u & 0x80000000u) ? __uint_as_float(u & 0x7FFFFFFFu) : __uint_as_float(~u);
}
__device__ __forceinline__ float lrelu(float x) { return x > 0.0f ? x : 0.01f * x; }

// ---------------- preprocessing: CSR build ----------------
// edge_index is int32, layout [2, E] row-major. Ee % 4 == 0.
__global__ void __launch_bounds__(256) count_kernel(const int* __restrict__ ei) {
    int i0 = (blockIdx.x * 256 + threadIdx.x) * 4;
    if (i0 + 3 < Ee) {
        int4 v = *reinterpret_cast<const int4*>(ei + i0);
        atomicAdd(&g_cnt[v.x], 1);
        atomicAdd(&g_cnt[v.y], 1);
        atomicAdd(&g_cnt[v.z], 1);
        atomicAdd(&g_cnt[v.w], 1);
    } else {
        for (int i = i0; i < Ee; i++) atomicAdd(&g_cnt[ei[i]], 1);
    }
}

// Single-block exclusive scan of g_cnt -> g_ptr, g_fill; also g_dis = cnt^{-1/2}.
__global__ void __launch_bounds__(1024) scan_kernel() {
    const int T = 1024;
    const int C = (Nn + T - 1) / T;  // 98
    int t = threadIdx.x;
    int base = t * C;
    int s = 0;
    for (int i = 0; i < C; i++) {
        int idx = base + i;
        if (idx < Nn) s += g_cnt[idx];
    }
    __shared__ int sh[T];
    sh[t] = s;
    __syncthreads();
    for (int off = 1; off < T; off <<= 1) {
        int v = (t >= off) ? sh[t - off] : 0;
        __syncthreads();
        sh[t] += v;
        __syncthreads();
    }
    int run = (t == 0) ? 0 : sh[t - 1];
    for (int i = 0; i < C; i++) {
        int idx = base + i;
        if (idx < Nn) {
            int cnt = g_cnt[idx];
            g_ptr[idx] = run;
            g_fill[idx] = run;
            g_dis[idx] = cnt > 0 ? rsqrtf((float)cnt) : 0.0f;
            run += cnt;
        }
    }
    if (t == T - 1) g_ptr[Nn] = run;  // == Ee
}

__global__ void __launch_bounds__(256) scatter_kernel(const int* __restrict__ ei) {
    int i0 = (blockIdx.x * 256 + threadIdx.x) * 4;
    if (i0 + 3 < Ee) {
        int4 rr = *reinterpret_cast<const int4*>(ei + i0);
        int4 cc = *reinterpret_cast<const int4*>(ei + Ee + i0);
        int p0 = atomicAdd(&g_fill[rr.x], 1);
        int p1 = atomicAdd(&g_fill[rr.y], 1);
        int p2 = atomicAdd(&g_fill[rr.z], 1);
        int p3 = atomicAdd(&g_fill[rr.w], 1);
        g_ccol[p0] = cc.x; g_cnorm[p0] = -g_dis[rr.x] * g_dis[cc.x];
        g_ccol[p1] = cc.y; g_cnorm[p1] = -g_dis[rr.y] * g_dis[cc.y];
        g_ccol[p2] = cc.z; g_cnorm[p2] = -g_dis[rr.z] * g_dis[cc.z];
        g_ccol[p3] = cc.w; g_cnorm[p3] = -g_dis[rr.w] * g_dis[cc.w];
    } else {
        for (int i = i0; i < Ee; i++) {
            int r = ei[i], c = ei[Ee + i];
            int pos = atomicAdd(&g_fill[r], 1);
            g_ccol[pos] = c;
            g_cnorm[pos] = -g_dis[r] * g_dis[c];
        }
    }
}

// ---------------- CSR propagation: dst[r] = sum_e norm[e] * src[col[e]] ----------------
// 16 threads per row (one float4 each); unroll-4 on edges (validated: 35 us). FROZEN.
__global__ void __launch_bounds__(256) prop_csr_kernel(const float* __restrict__ src,
                                                       float* __restrict__ dst) {
    int r = blockIdx.x * 16 + (threadIdx.x >> 4);
    int q = threadIdx.x & 15;
    if (r >= Nn) return;
    int s = g_ptr[r];
    int e = g_ptr[r + 1];
    const float4* __restrict__ src4 = reinterpret_cast<const float4*>(src);
    float4 acc = make_float4(0.f, 0.f, 0.f, 0.f);
    int i = s;
    for (; i + 4 <= e; i += 4) {
        int   c0 = __ldg(&g_ccol[i]),     c1 = __ldg(&g_ccol[i + 1]);
        int   c2 = __ldg(&g_ccol[i + 2]), c3 = __ldg(&g_ccol[i + 3]);
        float n0 = __ldg(&g_cnorm[i]),     n1 = __ldg(&g_cnorm[i + 1]);
        float n2 = __ldg(&g_cnorm[i + 2]), n3 = __ldg(&g_cnorm[i + 3]);
        float4 v0 = __ldg(&src4[c0 * 16 + q]);
        float4 v1 = __ldg(&src4[c1 * 16 + q]);
        float4 v2 = __ldg(&src4[c2 * 16 + q]);
        float4 v3 = __ldg(&src4[c3 * 16 + q]);
        acc.x += n0 * v0.x + n1 * v1.x + n2 * v2.x + n3 * v3.x;
        acc.y += n0 * v0.y + n1 * v1.y + n2 * v2.y + n3 * v3.y;
        acc.z += n0 * v0.z + n1 * v1.z + n2 * v2.z + n3 * v3.z;
        acc.w += n0 * v0.w + n1 * v1.w + n2 * v2.w + n3 * v3.w;
    }
    for (; i < e; i++) {
        int   c = __ldg(&g_ccol[i]);
        float n = __ldg(&g_cnorm[i]);
        float4 v = __ldg(&src4[c * 16 + q]);
        acc.x += n * v.x;
        acc.y += n * v.y;
        acc.z += n * v.z;
        acc.w += n * v.w;
    }
    reinterpret_cast<float4*>(dst)[r * 16 + q] = acc;
}

// ---------------- combined ChebConv weight ----------------
// out = Tx0@(W0 - W2) + Tx1@W1 + prop(Tx1)@(2*W2)
__global__ void combine_wc_kernel(const float* __restrict__ w) {
    int idx = blockIdx.x * blockDim.x + threadIdx.x;
    if (idx >= 192 * 64) return;
    int kk = idx >> 6, j = idx & 63;
    float v;
    if (kk < 64)        v = w[kk * 64 + j] - w[2 * 4096 + kk * 64 + j];
    else if (kk < 128)  v = w[4096 + (kk - 64) * 64 + j];
    else                v = 2.0f * w[2 * 4096 + (kk - 128) * 64 + j];
    g_Wc[idx] = v;
}

// ---------------- fused 3-term GEMM, 8x8 register tiling + fused BN stats ----------------
// 256 threads, 256 rows/block (PROVEN at R11). After the output store, each
// thread reduces its 8x8 tile into per-feature sum/sumsq, shfl-reduces across
// the 4 lanes sharing a feature group, and lanes<8 flush to g_stats atomics.
// Dynamic smem: sW 192*64 f (48 KB) + sX 64*256 f (64 KB) = 114688 B.
__global__ void __launch_bounds__(256, 2) gemm3_kernel(const float* __restrict__ s0,
                                                       const float* __restrict__ s1,
                                                       const float* __restrict__ s2,
                                                       const float* __restrict__ bias,
                                                       float* __restrict__ out) {
    extern __shared__ float dyn[];
    float* sW = dyn;               // [k 0..191][col 0..63]
    float* sX = dyn + 192 * 64;    // [k 0..63][row 0..255]
    int tid = threadIdx.x;

    // stage W (natural layout == g_Wc layout)
    const float4* gW = reinterpret_cast<const float4*>(g_Wc);
    float4* sW4 = reinterpret_cast<float4*>(sW);
#pragma unroll
    for (int i = 0; i < 12; i++) sW4[tid + 256 * i] = gW[tid + 256 * i];

    int ry = tid >> 3;   // 0..31 row-tile (8 rows each)
    int cx = tid & 7;    // 0..7 col-tile (8 cols each)
    int rowBase = blockIdx.x * 256;

    float acc[8][8];
#pragma unroll
    for (int j = 0; j < 8; j++) {
        float b = __ldg(&bias[cx * 8 + j]);
#pragma unroll
        for (int i = 0; i < 8; i++) acc[i][j] = b;
    }

    const float* srcs[3] = {s0, s1, s2};
#pragma unroll 1
    for (int s = 0; s < 3; s++) {
        __syncthreads();   // previous compute done (and sW staged on s=0)
        // stage source s transposed: thread stages row rowBase+tid
        {
            int r = rowBase + tid;
            const float4* p = reinterpret_cast<const float4*>(srcs[s] + (size_t)r * 64);
            bool ok = r < Nn;
#pragma unroll
            for (int k4 = 0; k4 < 16; k4++) {
                float4 v = ok ? __ldg(&p[k4]) : make_float4(0.f, 0.f, 0.f, 0.f);
                sX[(k4 * 4 + 0) * 256 + tid] = v.x;
                sX[(k4 * 4 + 1) * 256 + tid] = v.y;
                sX[(k4 * 4 + 2) * 256 + tid] = v.z;
                sX[(k4 * 4 + 3) * 256 + tid] = v.w;
            }
        }
        __syncthreads();
#pragma unroll 1
        for (int k = 0; k < 64; k++) {
            float4 va = *reinterpret_cast<const float4*>(&sX[k * 256 + ry * 8]);
            float4 vb = *reinterpret_cast<const float4*>(&sX[k * 256 + ry * 8 + 4]);
            float4 wa = *reinterpret_cast<const float4*>(&sW[(s * 64 + k) * 64 + cx * 8]);
            float4 wb = *reinterpret_cast<const float4*>(&sW[(s * 64 + k) * 64 + cx * 8 + 4]);
            float v[8] = {va.x, va.y, va.z, va.w, vb.x, vb.y, vb.z, vb.w};
            float w[8] = {wa.x, wa.y, wa.z, wa.w, wb.x, wb.y, wb.z, wb.w};
#pragma unroll
            for (int i = 0; i < 8; i++)
#pragma unroll
                for (int j = 0; j < 8; j++)
                    acc[i][j] += v[i] * w[j];
        }
    }
#pragma unroll
    for (int i = 0; i < 8; i++) {
        int r = rowBase + ry * 8 + i;
        if (r < Nn) {
            float4* po = reinterpret_cast<float4*>(out + (size_t)r * 64 + cx * 8);
            po[0] = make_float4(acc[i][0], acc[i][1], acc[i][2], acc[i][3]);
            po[1] = make_float4(acc[i][4], acc[i][5], acc[i][6], acc[i][7]);
        }
    }

    // ---- fused BN statistics (valid rows only) ----
    float cs[8], cq[8];
#pragma unroll
    for (int j = 0; j < 8; j++) { cs[j] = 0.f; cq[j] = 0.f; }
#pragma unroll
    for (int i = 0; i < 8; i++) {
        int r = rowBase + ry * 8 + i;
        if (r < Nn) {
#pragma unroll
            for (int j = 0; j < 8; j++) {
                float v = acc[i][j];
                cs[j] += v;
                cq[j] = fmaf(v, v, cq[j]);
            }
        }
    }
    // lanes (cx, cx+8, cx+16, cx+24) share a feature group -> xor-reduce 8,16
#pragma unroll
    for (int j = 0; j < 8; j++) {
        cs[j] += __shfl_xor_sync(0xFFFFFFFFu, cs[j], 8);
        cq[j] += __shfl_xor_sync(0xFFFFFFFFu, cq[j], 8);
        cs[j] += __shfl_xor_sync(0xFFFFFFFFu, cs[j], 16);
        cq[j] += __shfl_xor_sync(0xFFFFFFFFu, cq[j], 16);
    }
    if ((tid & 31) < 8) {
#pragma unroll
        for (int j = 0; j < 8; j++) {
            atomicAdd(&g_stats[cx * 8 + j], cs[j]);
            atomicAdd(&g_stats[64 + cx * 8 + j], cq[j]);
        }
    }
}

// ---------------- shortcut GEMM, 8x8 register tiling (PROVEN, untouched) ----------------
// Dynamic smem: sW 64*64 f (16 KB) + sX 64*256 f (64 KB) = 81920 B.
__global__ void __launch_bounds__(256, 2) gemm1_kernel(const float* __restrict__ s0,
                                                       const float* __restrict__ wsc,
                                                       const float* __restrict__ bias,
                                                       float* __restrict__ out) {
    extern __shared__ float dyn[];
    float* sW = dyn;               // [k 0..63][col 0..63]
    float* sX = dyn + 64 * 64;     // [k 0..63][row 0..255]
    int tid = threadIdx.x;

    const float4* gW = reinterpret_cast<const float4*>(wsc);
    float4* sW4 = reinterpret_cast<float4*>(sW);
#pragma unroll
    for (int i = 0; i < 4; i++) sW4[tid + 256 * i] = __ldg(&gW[tid + 256 * i]);

    int ry = tid >> 3;
    int cx = tid & 7;
    int rowBase = blockIdx.x * 256;

    float acc[8][8];
#pragma unroll
    for (int j = 0; j < 8; j++) {
        float b = __ldg(&bias[cx * 8 + j]);
#pragma unroll
        for (int i = 0; i < 8; i++) acc[i][j] = b;
    }

    {
        int r = rowBase + tid;
        const float4* p = reinterpret_cast<const float4*>(s0 + (size_t)r * 64);
        bool ok = r < Nn;
#pragma unroll
        for (int k4 = 0; k4 < 16; k4++) {
            float4 v = ok ? __ldg(&p[k4]) : make_float4(0.f, 0.f, 0.f, 0.f);
            sX[(k4 * 4 + 0) * 256 + tid] = v.x;
            sX[(k4 * 4 + 1) * 256 + tid] = v.y;
            sX[(k4 * 4 + 2) * 256 + tid] = v.z;
            sX[(k4 * 4 + 3) * 256 + tid] = v.w;
        }
    }
    __syncthreads();

#pragma unroll 1
    for (int k = 0; k < 64; k++) {
        float4 va = *reinterpret_cast<const float4*>(&sX[k * 256 + ry * 8]);
        float4 vb = *reinterpret_cast<const float4*>(&sX[k * 256 + ry * 8 + 4]);
        float4 wa = *reinterpret_cast<const float4*>(&sW[k * 64 + cx * 8]);
        float4 wb = *reinterpret_cast<const float4*>(&sW[k * 64 + cx * 8 + 4]);
        float v[8] = {va.x, va.y, va.z, va.w, vb.x, vb.y, vb.z, vb.w};
        float w[8] = {wa.x, wa.y, wa.z, wa.w, wb.x, wb.y, wb.z, wb.w};
#pragma unroll
        for (int i = 0; i < 8; i++)
#pragma unroll
            for (int j = 0; j < 8; j++)
                acc[i][j] += v[i] * w[j];
    }
#pragma unroll
    for (int i = 0; i < 8; i++) {
        int r = rowBase + ry * 8 + i;
        if (r < Nn) {
            float4* po = reinterpret_cast<float4*>(out + (size_t)r * 64 + cx * 8);
            po[0] = make_float4(acc[i][0], acc[i][1], acc[i][2], acc[i][3]);
            po[1] = make_float4(acc[i][4], acc[i][5], acc[i][6], acc[i][7]);
        }
    }
}

// ---------------- finalize BN affine ----------------
__global__ void finalize_kernel(const float* __restrict__ gamma,
                                const float* __restrict__ beta) {
    int j = threadIdx.x;
    if (j >= 64) return;
    float mu  = g_stats[j] * (1.0f / (float)Nn);
    float var = g_stats[64 + j] * (1.0f / (float)Nn) - mu * mu;
    var = fmaxf(var, 0.0f);
    float a = gamma[j] * rsqrtf(var + 1e-5f);
    g_ab[j] = a;
    g_ab[64 + j] = beta[j] - mu * a;
}

// ---------------- BN apply + LeakyReLU (layers 1 & 2) ----------------
__global__ void __launch_bounds__(256) apply_kernel(const float* __restrict__ hpre,
                                                    float* __restrict__ h) {
    int idx = blockIdx.x * blockDim.x + threadIdx.x;  // Nn*16 float4
    if (idx >= Nn * 16) return;
    int j4 = idx & 15;
    float4 a = reinterpret_cast<const float4*>(g_ab)[j4];
    float4 c = reinterpret_cast<const float4*>(g_ab + 64)[j4];
    float4 v = reinterpret_cast<const float4*>(hpre)[idx];
    float4 o;
    o.x = lrelu(v.x * a.x + c.x);
    o.y = lrelu(v.y * a.y + c.y);
    o.z = lrelu(v.z * a.z + c.z);
    o.w = lrelu(v.w * a.w + c.w);
    reinterpret_cast<float4*>(h)[idx] = o;
}

// ---------------- layer 3: BN apply + LeakyReLU + shortcut + segment_max pooling ----------------
__global__ void __launch_bounds__(256) apply3_pool_kernel(const int* __restrict__ batch,
                                                          const float* __restrict__ hpre,
                                                          const float* __restrict__ sc) {
    int idx = blockIdx.x * 256 + threadIdx.x;  // exactly Nn*16 = 6250 blocks
    int j4 = idx & 15;
    int r = idx >> 4;
    float4 a = reinterpret_cast<const float4*>(g_ab)[j4];
    float4 c = reinterpret_cast<const float4*>(g_ab + 64)[j4];
    float4 v = reinterpret_cast<const float4*>(hpre)[idx];
    float4 s = reinterpret_cast<const float4*>(sc)[idx];
    float4 h;
    h.x = lrelu(v.x * a.x + c.x) + s.x;
    h.y = lrelu(v.y * a.y + c.y) + s.y;
    h.z = lrelu(v.z * a.z + c.z) + s.z;
    h.w = lrelu(v.w * a.w + c.w) + s.w;

    __shared__ float4 sv[256];
    sv[threadIdx.x] = h;
    int row0 = blockIdx.x * 16;
    __syncthreads();

    int b0 = batch[row0];
    int bL = batch[row0 + 15];
    if (b0 == bL) {
        if (threadIdx.x < 64) {
            int slot = threadIdx.x;
            const float* svf = reinterpret_cast<const float*>(sv);
            float m = svf[slot];
#pragma unroll
            for (int rr = 1; rr < 16; rr++) m = fmaxf(m, svf[rr * 64 + slot]);
            atomicMax(&g_pool[b0 * 64 + slot], enc_f(m));
        }
    } else {
        int b = batch[r];
        atomicMax(&g_pool[b * 64 + j4 * 4 + 0], enc_f(h.x));
        atomicMax(&g_pool[b * 64 + j4 * 4 + 1], enc_f(h.y));
        atomicMax(&g_pool[b * 64 + j4 * 4 + 2], enc_f(h.z));
        atomicMax(&g_pool[b * 64 + j4 * 4 + 3], enc_f(h.w));
    }
}

// ---------------- final: out[g] = pooled[g,:] @ w_lin + b_lin ----------------
__global__ void final_kernel(const float* __restrict__ wl,
                             const float* __restrict__ bl,
                             float* __restrict__ out) {
    int g = blockIdx.x;
    int j = threadIdx.x;
    float v = dec_f(g_pool[g * 64 + j]) * wl[j];
    __shared__ float sred[64];
    sred[j] = v;
    __syncthreads();
    if (j < 32) {
        float t = sred[j] + sred[j + 32];
#pragma unroll
        for (int off = 16; off > 0; off >>= 1) t += __shfl_down_sync(0xFFFFFFFFu, t, off);
        if (j == 0) out[g] = t + bl[0];
    }
}

// ---------------- host launcher ----------------
extern "C" void kernel_launch(void* const* d_in, const int* in_sizes, int n_in,
                              void* d_out, int out_size) {
    (void)in_sizes; (void)n_in; (void)out_size;
    const float* x     = (const float*)d_in[0];
    const int*   ei    = (const int*)d_in[1];      // int32 (JAX x64 disabled)
    const int*   batch = (const int*)d_in[2];      // int32
    const float* w1 = (const float*)d_in[3];
    const float* b1 = (const float*)d_in[4];
    const float* w2 = (const float*)d_in[5];
    const float* b2 = (const float*)d_in[6];
    const float* w3 = (const float*)d_in[7];
    const float* b3 = (const float*)d_in[8];
    const float* g1 = (const float*)d_in[9];
    const float* be1 = (const float*)d_in[10];
    const float* g2 = (const float*)d_in[11];
    const float* be2 = (const float*)d_in[12];
    const float* g3 = (const float*)d_in[13];
    const float* be3 = (const float*)d_in[14];
    const float* w_sc = (const float*)d_in[15];
    const float* b_sc = (const float*)d_in[16];
    const float* w_lin = (const float*)d_in[17];
    const float* b_lin = (const float*)d_in[18];
    float* out = (float*)d_out;

    // Opt-in dynamic smem (host-side attribute set; capture-safe, idempotent)
    cudaFuncSetAttribute(gemm3_kernel, cudaFuncAttributeMaxDynamicSharedMemorySize, 114688);
    cudaFuncSetAttribute(gemm1_kernel, cudaFuncAttributeMaxDynamicSharedMemorySize, 81920);

    void *p_cnt, *p_T1, *p_Tmp, *p_hpre, *p_h, *p_sc, *p_stats, *p_pool;
    cudaGetSymbolAddress(&p_cnt, g_cnt);
    cudaGetSymbolAddress(&p_T1, g_T1);
    cudaGetSymbolAddress(&p_Tmp, g_Tmp);
    cudaGetSymbolAddress(&p_hpre, g_hpre);
    cudaGetSymbolAddress(&p_h, g_h);
    cudaGetSymbolAddress(&p_sc, g_sc);
    cudaGetSymbolAddress(&p_stats, g_stats);
    cudaGetSymbolAddress(&p_pool, g_pool);

    const float* f_T1   = (const float*)p_T1;
    const float* f_Tmp  = (const float*)p_Tmp;
    const float* f_hpre = (const float*)p_hpre;
    const float* f_h    = (const float*)p_h;
    const float* f_sc   = (const float*)p_sc;

    const int EB4 = (Ee / 4 + 255) / 256;     // 1563
    const int GB = (Nn + 255) / 256;          // 391 (GEMMs: 256 rows/block)
    const int RB = Nn / 16;                   // 6250 (prop: 16 rows/block)
    const int AB = (Nn * 16 + 255) / 256;     // 6250

    // --- CSR build; gemm1 sits at profiled launch slot 5 (regression guard) ---
    cudaMemsetAsync(p_cnt, 0, Nn * sizeof(int));
    count_kernel<<<EB4, 256>>>(ei);
    scan_kernel<<<1, 1024>>>();
    scatter_kernel<<<EB4, 256>>>(ei);
    gemm1_kernel<<<GB, 256, 81920>>>(x, w_sc, b_sc, (float*)p_sc);
    cudaMemsetAsync(p_pool, 0, Gg * 64 * sizeof(unsigned));

    const float* layer_in = x;
    const float* Ws[3] = {w1, w2, w3};
    const float* Bs[3] = {b1, b2, b3};
    const float* Gs[3] = {g1, g2, g3};
    const float* BEs[3] = {be1, be2, be3};

    for (int L = 0; L < 3; L++) {
        prop_csr_kernel<<<RB, 256>>>(layer_in, (float*)p_T1);
        prop_csr_kernel<<<RB, 256>>>(f_T1, (float*)p_Tmp);
        combine_wc_kernel<<<48, 256>>>(Ws[L]);
        cudaMemsetAsync(p_stats, 0, 128 * sizeof(float));
        gemm3_kernel<<<GB, 256, 114688>>>(layer_in, f_T1, f_Tmp, Bs[L], (float*)p_hpre);
        finalize_kernel<<<1, 64>>>(Gs[L], BEs[L]);
        if (L < 2) {
            apply_kernel<<<AB, 256>>>(f_hpre, (float*)p_h);
            layer_in = f_h;
        } else {
            apply3_pool_kernel<<<AB, 256>>>(batch, f_hpre, f_sc);
        }
    }

    final_kernel<<<Gg, 64>>>(w_lin, b_lin, out);
}

// round 13
// speedup vs baseline: 1.2673x; 1.2673x over previous
#include <cuda_runtime.h>
#include <cstdint>
#include <cstdio>

// Problem constants (fixed by the reference)
#define Nn 100000
#define Ee 1600000
#define Hh 64
#define Gg 64

// ---------------- static device scratch (no allocations allowed) ----------------
__device__ int      g_cnt[Nn];        // per-row edge count
__device__ int      g_ptr[Nn + 1];    // CSR row pointers
__device__ int      g_fill[Nn];       // scatter cursors
__device__ float    g_dis[Nn];        // deg^{-1/2}
__device__ int      g_ccol[Ee];       // CSR col indices
__device__ float    g_cnorm[Ee];      // CSR edge weights (-dis[r]*dis[c])
__device__ float    g_T1 [Nn * Hh];
__device__ float    g_Tmp[Nn * Hh];
__device__ float    g_hpre[Nn * Hh];
__device__ float    g_h  [Nn * Hh];
__device__ float    g_sc [Nn * Hh];
__device__ float    g_stats[128];     // [0:64) sum, [64:128) sumsq
__device__ float    g_ab[128];        // [0:64) scale a, [64:128) shift c
__device__ unsigned g_pool[Gg * 64];

// ---------------- helpers ----------------
__device__ __forceinline__ unsigned enc_f(float f) {
    unsigned u = __float_as_uint(f);
    return (u & 0x80000000u) ? ~u : (u | 0x80000000u);
}
__device__ __forceinline__ float dec_f(unsigned u) {
    return (u & 0x80000000u) ? __uint_as_float(u & 0x7FFFFFFFu) : __uint_as_float(~u);
}
__device__ __forceinline__ float lrelu(float x) { return x > 0.0f ? x : 0.01f * x; }

// ---------------- preprocessing: CSR build ----------------
// edge_index is int32, layout [2, E] row-major. Ee % 4 == 0.
__global__ void __launch_bounds__(256) count_kernel(const int* __restrict__ ei) {
    int i0 = (blockIdx.x * 256 + threadIdx.x) * 4;
    if (i0 + 3 < Ee) {
        int4 v = *reinterpret_cast<const int4*>(ei + i0);
        atomicAdd(&g_cnt[v.x], 1);
        atomicAdd(&g_cnt[v.y], 1);
        atomicAdd(&g_cnt[v.z], 1);
        atomicAdd(&g_cnt[v.w], 1);
    } else {
        for (int i = i0; i < Ee; i++) atomicAdd(&g_cnt[ei[i]], 1);
    }
}

// Single-block exclusive scan of g_cnt -> g_ptr, g_fill; also g_dis = cnt^{-1/2}.
__global__ void __launch_bounds__(1024) scan_kernel() {
    const int T = 1024;
    const int C = (Nn + T - 1) / T;  // 98
    int t = threadIdx.x;
    int base = t * C;
    int s = 0;
    for (int i = 0; i < C; i++) {
        int idx = base + i;
        if (idx < Nn) s += g_cnt[idx];
    }
    __shared__ int sh[T];
    sh[t] = s;
    __syncthreads();
    for (int off = 1; off < T; off <<= 1) {
        int v = (t >= off) ? sh[t - off] : 0;
        __syncthreads();
        sh[t] += v;
        __syncthreads();
    }
    int run = (t == 0) ? 0 : sh[t - 1];
    for (int i = 0; i < C; i++) {
        int idx = base + i;
        if (idx < Nn) {
            int cnt = g_cnt[idx];
            g_ptr[idx] = run;
            g_fill[idx] = run;
            g_dis[idx] = cnt > 0 ? rsqrtf((float)cnt) : 0.0f;
            run += cnt;
        }
    }
    if (t == T - 1) g_ptr[Nn] = run;  // == Ee
}

__global__ void __launch_bounds__(256) scatter_kernel(const int* __restrict__ ei) {
    int i0 = (blockIdx.x * 256 + threadIdx.x) * 4;
    if (i0 + 3 < Ee) {
        int4 rr = *reinterpret_cast<const int4*>(ei + i0);
        int4 cc = *reinterpret_cast<const int4*>(ei + Ee + i0);
        int p0 = atomicAdd(&g_fill[rr.x], 1);
        int p1 = atomicAdd(&g_fill[rr.y], 1);
        int p2 = atomicAdd(&g_fill[rr.z], 1);
        int p3 = atomicAdd(&g_fill[rr.w], 1);
        g_ccol[p0] = cc.x; g_cnorm[p0] = -g_dis[rr.x] * g_dis[cc.x];
        g_ccol[p1] = cc.y; g_cnorm[p1] = -g_dis[rr.y] * g_dis[cc.y];
        g_ccol[p2] = cc.z; g_cnorm[p2] = -g_dis[rr.z] * g_dis[cc.z];
        g_ccol[p3] = cc.w; g_cnorm[p3] = -g_dis[rr.w] * g_dis[cc.w];
    } else {
        for (int i = i0; i < Ee; i++) {
            int r = ei[i], c = ei[Ee + i];
            int pos = atomicAdd(&g_fill[r], 1);
            g_ccol[pos] = c;
            g_cnorm[pos] = -g_dis[r] * g_dis[c];
        }
    }
}

// ---------------- CSR propagation: dst[r] = sum_e norm[e] * src[col[e]] ----------------
// 16 threads per row (one float4 each); unroll-4 on edges (validated: 35 us). FROZEN.
__global__ void __launch_bounds__(256) prop_csr_kernel(const float* __restrict__ src,
                                                       float* __restrict__ dst) {
    int r = blockIdx.x * 16 + (threadIdx.x >> 4);
    int q = threadIdx.x & 15;
    if (r >= Nn) return;
    int s = g_ptr[r];
    int e = g_ptr[r + 1];
    const float4* __restrict__ src4 = reinterpret_cast<const float4*>(src);
    float4 acc = make_float4(0.f, 0.f, 0.f, 0.f);
    int i = s;
    for (; i + 4 <= e; i += 4) {
        int   c0 = __ldg(&g_ccol[i]),     c1 = __ldg(&g_ccol[i + 1]);
        int   c2 = __ldg(&g_ccol[i + 2]), c3 = __ldg(&g_ccol[i + 3]);
        float n0 = __ldg(&g_cnorm[i]),     n1 = __ldg(&g_cnorm[i + 1]);
        float n2 = __ldg(&g_cnorm[i + 2]), n3 = __ldg(&g_cnorm[i + 3]);
        float4 v0 = __ldg(&src4[c0 * 16 + q]);
        float4 v1 = __ldg(&src4[c1 * 16 + q]);
        float4 v2 = __ldg(&src4[c2 * 16 + q]);
        float4 v3 = __ldg(&src4[c3 * 16 + q]);
        acc.x += n0 * v0.x + n1 * v1.x + n2 * v2.x + n3 * v3.x;
        acc.y += n0 * v0.y + n1 * v1.y + n2 * v2.y + n3 * v3.y;
        acc.z += n0 * v0.z + n1 * v1.z + n2 * v2.z + n3 * v3.z;
        acc.w += n0 * v0.w + n1 * v1.w + n2 * v2.w + n3 * v3.w;
    }
    for (; i < e; i++) {
        int   c = __ldg(&g_ccol[i]);
        float n = __ldg(&g_cnorm[i]);
        float4 v = __ldg(&src4[c * 16 + q]);
        acc.x += n * v.x;
        acc.y += n * v.y;
        acc.z += n * v.z;
        acc.w += n * v.w;
    }
    reinterpret_cast<float4*>(dst)[r * 16 + q] = acc;
}

// ---------------- fused 3-term GEMM, 8x8 register tiling (R11-PROVEN core) ----------------
// Weight combination (W0-W2 | W1 | 2*W2) is computed on the fly during sW
// staging (uniform branches per unroll step) -> no combine_wc kernel.
// Dynamic smem: sW 192*64 f (48 KB) + sX 64*256 f (64 KB) = 114688 B.
__global__ void __launch_bounds__(256, 2) gemm3_kernel(const float* __restrict__ s0,
                                                       const float* __restrict__ s1,
                                                       const float* __restrict__ s2,
                                                       const float* __restrict__ w,
                                                       const float* __restrict__ bias,
                                                       float* __restrict__ out) {
    extern __shared__ float dyn[];
    float* sW = dyn;               // [k 0..191][col 0..63]
    float* sX = dyn + 192 * 64;    // [k 0..63][row 0..255]
    int tid = threadIdx.x;

    // stage combined W from raw w [3][64][64]
    const float4* w4 = reinterpret_cast<const float4*>(w);   // matrix k at offset k*1024 f4
    float4* sW4 = reinterpret_cast<float4*>(sW);
#pragma unroll
    for (int i = 0; i < 12; i++) {
        int idx = tid + 256 * i;   // 0..3071
        int kk = idx >> 4;         // 0..191
        int j4 = idx & 15;
        float4 v;
        if (kk < 64) {
            float4 a = __ldg(&w4[kk * 16 + j4]);
            float4 b = __ldg(&w4[2048 + kk * 16 + j4]);
            v = make_float4(a.x - b.x, a.y - b.y, a.z - b.z, a.w - b.w);
        } else if (kk < 128) {
            v = __ldg(&w4[1024 + (kk - 64) * 16 + j4]);
        } else {
            float4 b = __ldg(&w4[2048 + (kk - 128) * 16 + j4]);
            v = make_float4(2.0f * b.x, 2.0f * b.y, 2.0f * b.z, 2.0f * b.w);
        }
        sW4[idx] = v;
    }

    int ry = tid >> 3;   // 0..31 row-tile (8 rows each)
    int cx = tid & 7;    // 0..7 col-tile (8 cols each)
    int rowBase = blockIdx.x * 256;

    float acc[8][8];
#pragma unroll
    for (int j = 0; j < 8; j++) {
        float b = __ldg(&bias[cx * 8 + j]);
#pragma unroll
        for (int i = 0; i < 8; i++) acc[i][j] = b;
    }

    const float* srcs[3] = {s0, s1, s2};
#pragma unroll 1
    for (int s = 0; s < 3; s++) {
        __syncthreads();   // previous compute done (and sW staged on s=0)
        // stage source s transposed: thread stages row rowBase+tid
        {
            int r = rowBase + tid;
            const float4* p = reinterpret_cast<const float4*>(srcs[s] + (size_t)r * 64);
            bool ok = r < Nn;
#pragma unroll
            for (int k4 = 0; k4 < 16; k4++) {
                float4 v = ok ? __ldg(&p[k4]) : make_float4(0.f, 0.f, 0.f, 0.f);
                sX[(k4 * 4 + 0) * 256 + tid] = v.x;
                sX[(k4 * 4 + 1) * 256 + tid] = v.y;
                sX[(k4 * 4 + 2) * 256 + tid] = v.z;
                sX[(k4 * 4 + 3) * 256 + tid] = v.w;
            }
        }
        __syncthreads();
#pragma unroll 1
        for (int k = 0; k < 64; k++) {
            float4 va = *reinterpret_cast<const float4*>(&sX[k * 256 + ry * 8]);
            float4 vb = *reinterpret_cast<const float4*>(&sX[k * 256 + ry * 8 + 4]);
            float4 wa = *reinterpret_cast<const float4*>(&sW[(s * 64 + k) * 64 + cx * 8]);
            float4 wb = *reinterpret_cast<const float4*>(&sW[(s * 64 + k) * 64 + cx * 8 + 4]);
            float v[8] = {va.x, va.y, va.z, va.w, vb.x, vb.y, vb.z, vb.w};
            float ww[8] = {wa.x, wa.y, wa.z, wa.w, wb.x, wb.y, wb.z, wb.w};
#pragma unroll
            for (int i = 0; i < 8; i++)
#pragma unroll
                for (int j = 0; j < 8; j++)
                    acc[i][j] += v[i] * ww[j];
        }
    }
#pragma unroll
    for (int i = 0; i < 8; i++) {
        int r = rowBase + ry * 8 + i;
        if (r < Nn) {
            float4* po = reinterpret_cast<float4*>(out + (size_t)r * 64 + cx * 8);
            po[0] = make_float4(acc[i][0], acc[i][1], acc[i][2], acc[i][3]);
            po[1] = make_float4(acc[i][4], acc[i][5], acc[i][6], acc[i][7]);
        }
    }
}

// ---------------- shortcut GEMM, 8x8 register tiling (PROVEN, untouched) ----------------
// Dynamic smem: sW 64*64 f (16 KB) + sX 64*256 f (64 KB) = 81920 B.
__global__ void __launch_bounds__(256, 2) gemm1_kernel(const float* __restrict__ s0,
                                                       const float* __restrict__ wsc,
                                                       const float* __restrict__ bias,
                                                       float* __restrict__ out) {
    extern __shared__ float dyn[];
    float* sW = dyn;               // [k 0..63][col 0..63]
    float* sX = dyn + 64 * 64;     // [k 0..63][row 0..255]
    int tid = threadIdx.x;

    const float4* gW = reinterpret_cast<const float4*>(wsc);
    float4* sW4 = reinterpret_cast<float4*>(sW);
#pragma unroll
    for (int i = 0; i < 4; i++) sW4[tid + 256 * i] = __ldg(&gW[tid + 256 * i]);

    int ry = tid >> 3;
    int cx = tid & 7;
    int rowBase = blockIdx.x * 256;

    float acc[8][8];
#pragma unroll
    for (int j = 0; j < 8; j++) {
        float b = __ldg(&bias[cx * 8 + j]);
#pragma unroll
        for (int i = 0; i < 8; i++) acc[i][j] = b;
    }

    {
        int r = rowBase + tid;
        const float4* p = reinterpret_cast<const float4*>(s0 + (size_t)r * 64);
        bool ok = r < Nn;
#pragma unroll
        for (int k4 = 0; k4 < 16; k4++) {
            float4 v = ok ? __ldg(&p[k4]) : make_float4(0.f, 0.f, 0.f, 0.f);
            sX[(k4 * 4 + 0) * 256 + tid] = v.x;
            sX[(k4 * 4 + 1) * 256 + tid] = v.y;
            sX[(k4 * 4 + 2) * 256 + tid] = v.z;
            sX[(k4 * 4 + 3) * 256 + tid] = v.w;
        }
    }
    __syncthreads();

#pragma unroll 1
    for (int k = 0; k < 64; k++) {
        float4 va = *reinterpret_cast<const float4*>(&sX[k * 256 + ry * 8]);
        float4 vb = *reinterpret_cast<const float4*>(&sX[k * 256 + ry * 8 + 4]);
        float4 wa = *reinterpret_cast<const float4*>(&sW[k * 64 + cx * 8]);
        float4 wb = *reinterpret_cast<const float4*>(&sW[k * 64 + cx * 8 + 4]);
        float v[8] = {va.x, va.y, va.z, va.w, vb.x, vb.y, vb.z, vb.w};
        float w[8] = {wa.x, wa.y, wa.z, wa.w, wb.x, wb.y, wb.z, wb.w};
#pragma unroll
        for (int i = 0; i < 8; i++)
#pragma unroll
            for (int j = 0; j < 8; j++)
                acc[i][j] += v[i] * w[j];
    }
#pragma unroll
    for (int i = 0; i < 8; i++) {
        int r = rowBase + ry * 8 + i;
        if (r < Nn) {
            float4* po = reinterpret_cast<float4*>(out + (size_t)r * 64 + cx * 8);
            po[0] = make_float4(acc[i][0], acc[i][1], acc[i][2], acc[i][3]);
            po[1] = make_float4(acc[i][4], acc[i][5], acc[i][6], acc[i][7]);
        }
    }
}

// ---------------- BN statistics (R4-proven scalar form) ----------------
__global__ void __launch_bounds__(256) stats_kernel(const float* __restrict__ h) {
    int j = threadIdx.x & 63;
    int r0 = blockIdx.x * 4 + (threadIdx.x >> 6);
    float s = 0.0f, s2 = 0.0f;
    for (int r = r0; r < Nn; r += gridDim.x * 4) {
        float v = h[(size_t)r * 64 + j];
        s += v;
        s2 += v * v;
    }
    __shared__ float sh[256], sh2[256];
    sh[threadIdx.x] = s;
    sh2[threadIdx.x] = s2;
    __syncthreads();
    if (threadIdx.x < 64) {
        float ts  = sh[threadIdx.x] + sh[threadIdx.x + 64] + sh[threadIdx.x + 128] + sh[threadIdx.x + 192];
        float ts2 = sh2[threadIdx.x] + sh2[threadIdx.x + 64] + sh2[threadIdx.x + 128] + sh2[threadIdx.x + 192];
        atomicAdd(&g_stats[j], ts);
        atomicAdd(&g_stats[64 + j], ts2);
    }
}

__global__ void finalize_kernel(const float* __restrict__ gamma,
                                const float* __restrict__ beta) {
    int j = threadIdx.x;
    if (j >= 64) return;
    float mu  = g_stats[j] * (1.0f / (float)Nn);
    float var = g_stats[64 + j] * (1.0f / (float)Nn) - mu * mu;
    var = fmaxf(var, 0.0f);
    float a = gamma[j] * rsqrtf(var + 1e-5f);
    g_ab[j] = a;
    g_ab[64 + j] = beta[j] - mu * a;
}

// ---------------- BN apply + LeakyReLU (layers 1 & 2) ----------------
__global__ void __launch_bounds__(256) apply_kernel(const float* __restrict__ hpre,
                                                    float* __restrict__ h) {
    int idx = blockIdx.x * blockDim.x + threadIdx.x;  // Nn*16 float4
    if (idx >= Nn * 16) return;
    int j4 = idx & 15;
    float4 a = reinterpret_cast<const float4*>(g_ab)[j4];
    float4 c = reinterpret_cast<const float4*>(g_ab + 64)[j4];
    float4 v = reinterpret_cast<const float4*>(hpre)[idx];
    float4 o;
    o.x = lrelu(v.x * a.x + c.x);
    o.y = lrelu(v.y * a.y + c.y);
    o.z = lrelu(v.z * a.z + c.z);
    o.w = lrelu(v.w * a.w + c.w);
    reinterpret_cast<float4*>(h)[idx] = o;
}

// ---------------- layer 3: BN apply + LeakyReLU + shortcut + segment_max pooling ----------------
__global__ void __launch_bounds__(256) apply3_pool_kernel(const int* __restrict__ batch,
                                                          const float* __restrict__ hpre,
                                                          const float* __restrict__ sc) {
    int idx = blockIdx.x * 256 + threadIdx.x;  // exactly Nn*16 = 6250 blocks
    int j4 = idx & 15;
    int r = idx >> 4;
    float4 a = reinterpret_cast<const float4*>(g_ab)[j4];
    float4 c = reinterpret_cast<const float4*>(g_ab + 64)[j4];
    float4 v = reinterpret_cast<const float4*>(hpre)[idx];
    float4 s = reinterpret_cast<const float4*>(sc)[idx];
    float4 h;
    h.x = lrelu(v.x * a.x + c.x) + s.x;
    h.y = lrelu(v.y * a.y + c.y) + s.y;
    h.z = lrelu(v.z * a.z + c.z) + s.z;
    h.w = lrelu(v.w * a.w + c.w) + s.w;

    __shared__ float4 sv[256];
    sv[threadIdx.x] = h;
    int row0 = blockIdx.x * 16;
    __syncthreads();

    int b0 = batch[row0];
    int bL = batch[row0 + 15];
    if (b0 == bL) {
        if (threadIdx.x < 64) {
            int slot = threadIdx.x;
            const float* svf = reinterpret_cast<const float*>(sv);
            float m = svf[slot];
#pragma unroll
            for (int rr = 1; rr < 16; rr++) m = fmaxf(m, svf[rr * 64 + slot]);
            atomicMax(&g_pool[b0 * 64 + slot], enc_f(m));
        }
    } else {
        int b = batch[r];
        atomicMax(&g_pool[b * 64 + j4 * 4 + 0], enc_f(h.x));
        atomicMax(&g_pool[b * 64 + j4 * 4 + 1], enc_f(h.y));
        atomicMax(&g_pool[b * 64 + j4 * 4 + 2], enc_f(h.z));
        atomicMax(&g_pool[b * 64 + j4 * 4 + 3], enc_f(h.w));
    }
}

// ---------------- final: out[g] = pooled[g,:] @ w_lin + b_lin ----------------
__global__ void final_kernel(const float* __restrict__ wl,
                             const float* __restrict__ bl,
                             float* __restrict__ out) {
    int g = blockIdx.x;
    int j = threadIdx.x;
    float v = dec_f(g_pool[g * 64 + j]) * wl[j];
    __shared__ float sred[64];
    sred[j] = v;
    __syncthreads();
    if (j < 32) {
        float t = sred[j] + sred[j + 32];
#pragma unroll
        for (int off = 16; off > 0; off >>= 1) t += __shfl_down_sync(0xFFFFFFFFu, t, off);
        if (j == 0) out[g] = t + bl[0];
    }
}

// ---------------- host launcher ----------------
extern "C" void kernel_launch(void* const* d_in, const int* in_sizes, int n_in,
                              void* d_out, int out_size) {
    (void)in_sizes; (void)n_in; (void)out_size;
    const float* x     = (const float*)d_in[0];
    const int*   ei    = (const int*)d_in[1];      // int32 (JAX x64 disabled)
    const int*   batch = (const int*)d_in[2];      // int32
    const float* w1 = (const float*)d_in[3];
    const float* b1 = (const float*)d_in[4];
    const float* w2 = (const float*)d_in[5];
    const float* b2 = (const float*)d_in[6];
    const float* w3 = (const float*)d_in[7];
    const float* b3 = (const float*)d_in[8];
    const float* g1 = (const float*)d_in[9];
    const float* be1 = (const float*)d_in[10];
    const float* g2 = (const float*)d_in[11];
    const float* be2 = (const float*)d_in[12];
    const float* g3 = (const float*)d_in[13];
    const float* be3 = (const float*)d_in[14];
    const float* w_sc = (const float*)d_in[15];
    const float* b_sc = (const float*)d_in[16];
    const float* w_lin = (const float*)d_in[17];
    const float* b_lin = (const float*)d_in[18];
    float* out = (float*)d_out;

    // Opt-in dynamic smem (host-side attribute set; capture-safe, idempotent)
    cudaFuncSetAttribute(gemm3_kernel, cudaFuncAttributeMaxDynamicSharedMemorySize, 114688);
    cudaFuncSetAttribute(gemm1_kernel, cudaFuncAttributeMaxDynamicSharedMemorySize, 81920);

    void *p_cnt, *p_T1, *p_Tmp, *p_hpre, *p_h, *p_sc, *p_stats, *p_pool;
    cudaGetSymbolAddress(&p_cnt, g_cnt);
    cudaGetSymbolAddress(&p_T1, g_T1);
    cudaGetSymbolAddress(&p_Tmp, g_Tmp);
    cudaGetSymbolAddress(&p_hpre, g_hpre);
    cudaGetSymbolAddress(&p_h, g_h);
    cudaGetSymbolAddress(&p_sc, g_sc);
    cudaGetSymbolAddress(&p_stats, g_stats);
    cudaGetSymbolAddress(&p_pool, g_pool);

    const float* f_T1   = (const float*)p_T1;
    const float* f_Tmp  = (const float*)p_Tmp;
    const float* f_hpre = (const float*)p_hpre;
    const float* f_h    = (const float*)p_h;
    const float* f_sc   = (const float*)p_sc;

    const int EB4 = (Ee / 4 + 255) / 256;     // 1563
    const int GB = (Nn + 255) / 256;          // 391 (GEMMs: 256 rows/block)
    const int RB = Nn / 16;                   // 6250 (prop: 16 rows/block)
    const int AB = (Nn * 16 + 255) / 256;     // 6250

    // --- CSR build; gemm1 sits at profiled launch slot 5 (regression guard) ---
    cudaMemsetAsync(p_cnt, 0, Nn * sizeof(int));
    count_kernel<<<EB4, 256>>>(ei);
    scan_kernel<<<1, 1024>>>();
    scatter_kernel<<<EB4, 256>>>(ei);
    gemm1_kernel<<<GB, 256, 81920>>>(x, w_sc, b_sc, (float*)p_sc);
    cudaMemsetAsync(p_pool, 0, Gg * 64 * sizeof(unsigned));

    const float* layer_in = x;
    const float* Ws[3] = {w1, w2, w3};
    const float* Bs[3] = {b1, b2, b3};
    const float* Gs[3] = {g1, g2, g3};
    const float* BEs[3] = {be1, be2, be3};

    for (int L = 0; L < 3; L++) {
        prop_csr_kernel<<<RB, 256>>>(layer_in, (float*)p_T1);
        prop_csr_kernel<<<RB, 256>>>(f_T1, (float*)p_Tmp);
        gemm3_kernel<<<GB, 256, 114688>>>(layer_in, f_T1, f_Tmp, Ws[L], Bs[L], (float*)p_hpre);
        cudaMemsetAsync(p_stats, 0, 128 * sizeof(float));
        stats_kernel<<<256, 256>>>(f_hpre);
        finalize_kernel<<<1, 64>>>(Gs[L], BEs[L]);
        if (L < 2) {
            apply_kernel<<<AB, 256>>>(f_hpre, (float*)p_h);
            layer_in = f_h;
        } else {
            apply3_pool_kernel<<<AB, 256>>>(batch, f_hpre, f_sc);
        }
    }

    final_kernel<<<Gg, 64>>>(w_lin, b_lin, out);
}